// round 1
// baseline (speedup 1.0000x reference)
#include <cuda_runtime.h>
#include <cuda_bf16.h>

// ---------------- problem constants ----------------
#define Bc   2
#define Tc   4096
#define Ec   512
#define Hc   8
#define Dc   64
#define FFc  2048
#define Lc   2
#define WINc 16
#define NW   33           // window width
#define ROWS (Bc*Tc)      // 8192
#define EPSc 1e-5f

// ---------------- scratch (static device globals; no allocation allowed) ----
__device__ float g_h [ROWS*Ec];    // LN output
__device__ float g_q [ROWS*Ec];
__device__ float g_k [ROWS*Ec];
__device__ float g_v [ROWS*Ec];
__device__ float g_ao[ROWS*Ec];    // attention output (pre-Wo)
__device__ float g_ff[ROWS*FFc];   // FFN hidden

// ---------------- embedding: x = tok_emb[tokens] + pos_emb ------------------
__global__ void embed_kernel(const int* __restrict__ tokens,
                             const float* __restrict__ tok_emb,
                             const float* __restrict__ pos_emb,
                             float* __restrict__ x) {
    int row = blockIdx.x;             // 0..ROWS-1  (b*T + t)
    int t   = row & (Tc - 1);
    int tok = tokens[row];
    int e   = threadIdx.x * 4;        // 128 threads * 4 = 512
    float4 a = *(const float4*)(tok_emb + (size_t)tok * Ec + e);
    float4 p = *(const float4*)(pos_emb + (size_t)t   * Ec + e);
    a.x += p.x; a.y += p.y; a.z += p.z; a.w += p.w;
    *(float4*)(x + (size_t)row * Ec + e) = a;
}

// ---------------- layernorm: warp per row (E=512, 16 elems/lane) ------------
__global__ void ln_kernel(const float* __restrict__ x,
                          const float* __restrict__ g,
                          const float* __restrict__ b,
                          float* __restrict__ y) {
    int warp = (blockIdx.x * blockDim.x + threadIdx.x) >> 5;
    int lane = threadIdx.x & 31;
    if (warp >= ROWS) return;
    const float* xr = x + (size_t)warp * Ec;
    float v[16];
    float s = 0.f;
#pragma unroll
    for (int i = 0; i < 16; i++) { v[i] = xr[lane + i * 32]; s += v[i]; }
#pragma unroll
    for (int o = 16; o > 0; o >>= 1) s += __shfl_xor_sync(0xffffffffu, s, o);
    float mean = s * (1.f / Ec);
    float ss = 0.f;
#pragma unroll
    for (int i = 0; i < 16; i++) { float d = v[i] - mean; ss += d * d; }
#pragma unroll
    for (int o = 16; o > 0; o >>= 1) ss += __shfl_xor_sync(0xffffffffu, ss, o);
    float inv = rsqrtf(ss * (1.f / Ec) + EPSc);
    float* yr = y + (size_t)warp * Ec;
#pragma unroll
    for (int i = 0; i < 16; i++) {
        int idx = lane + i * 32;
        yr[idx] = (v[i] - mean) * inv * g[idx] + b[idx];
    }
}

// ---------------- SGEMM: C[M,N] = A[M,K] @ B[K,N] (+bias/relu/residual) -----
// EPI: 0 = plain (no bias), 1 = bias+relu, 2 = bias+residual
#define BM 128
#define BN 128
#define BKK 8
#define TM 8
#define TN 8

template <int EPI>
__global__ __launch_bounds__(256)
void sgemm_kernel(const float* __restrict__ A, const float* __restrict__ B,
                  const float* __restrict__ bias, const float* __restrict__ res,
                  float* __restrict__ C, int M, int N, int K) {
    __shared__ float As[BKK][BM];
    __shared__ float Bs[BKK][BN];

    int tid = threadIdx.x;
    int bx = blockIdx.x;   // N tile
    int by = blockIdx.y;   // M tile

    int tx = tid & 15;     // 0..15
    int ty = tid >> 4;     // 0..15

    int aRow = tid >> 1;          // 0..127
    int aCol = (tid & 1) * 4;     // 0 or 4
    int bRow = tid >> 5;          // 0..7
    int bCol = (tid & 31) * 4;    // 0..124

    const float* Aptr = A + (size_t)(by * BM + aRow) * K + aCol;
    const float* Bptr = B + (size_t)bRow * N + bx * BN + bCol;

    float acc[TM][TN];
#pragma unroll
    for (int i = 0; i < TM; i++)
#pragma unroll
        for (int j = 0; j < TN; j++) acc[i][j] = 0.f;

    for (int k0 = 0; k0 < K; k0 += BKK) {
        float4 a4 = *(const float4*)(Aptr + k0);
        As[aCol + 0][aRow] = a4.x;
        As[aCol + 1][aRow] = a4.y;
        As[aCol + 2][aRow] = a4.z;
        As[aCol + 3][aRow] = a4.w;
        float4 b4 = *(const float4*)(Bptr + (size_t)k0 * N);
        *(float4*)&Bs[bRow][bCol] = b4;
        __syncthreads();

#pragma unroll
        for (int kk = 0; kk < BKK; kk++) {
            float ar[TM], br[TN];
#pragma unroll
            for (int i = 0; i < TM; i++) ar[i] = As[kk][ty * TM + i];
#pragma unroll
            for (int j = 0; j < TN; j++) br[j] = Bs[kk][tx * TN + j];
#pragma unroll
            for (int i = 0; i < TM; i++)
#pragma unroll
                for (int j = 0; j < TN; j++) acc[i][j] += ar[i] * br[j];
        }
        __syncthreads();
    }

    int crow0 = by * BM + ty * TM;
    int ccol0 = bx * BN + tx * TN;
#pragma unroll
    for (int i = 0; i < TM; i++) {
        int row = crow0 + i;
        float* crow = C + (size_t)row * N;
        const float* rrow = (EPI == 2) ? (res + (size_t)row * N) : nullptr;
#pragma unroll
        for (int j = 0; j < TN; j++) {
            int col = ccol0 + j;
            float vv = acc[i][j];
            if (EPI >= 1) vv += bias[col];
            if (EPI == 1) vv = fmaxf(vv, 0.f);
            if (EPI == 2) vv += rrow[col];
            crow[col] = vv;
        }
    }
}

// ---------------- sliding-window attention: one warp per (b,t,h) ------------
__global__ void attn_kernel(const float* __restrict__ q,
                            const float* __restrict__ k,
                            const float* __restrict__ v,
                            const int* __restrict__ mask,
                            float* __restrict__ out) {
    int wg   = (blockIdx.x * blockDim.x + threadIdx.x) >> 5;  // 0..65535
    int lane = threadIdx.x & 31;
    int h = wg & (Hc - 1);
    int t = (wg >> 3) & (Tc - 1);
    int b = wg >> 15;

    const float* qr = q + ((size_t)(b * Tc + t) * Ec) + h * Dc;
    float q0 = qr[lane], q1 = qr[lane + 32];

    float sc[NW];
#pragma unroll
    for (int w = 0; w < NW; w++) {
        int tc = t + w - WINc;
        float s = -1e9f;
        if (tc >= 0 && tc < Tc && mask[b * Tc + tc] > 0) {
            const float* kr = k + ((size_t)(b * Tc + tc) * Ec) + h * Dc;
            float p = q0 * kr[lane] + q1 * kr[lane + 32];
#pragma unroll
            for (int o = 16; o > 0; o >>= 1) p += __shfl_xor_sync(0xffffffffu, p, o);
            s = p * 0.125f;   // 1/sqrt(64)
        }
        sc[w] = s;
    }

    float m = -1e9f;
#pragma unroll
    for (int w = 0; w < NW; w++) m = fmaxf(m, sc[w]);
    float sum = 0.f;
#pragma unroll
    for (int w = 0; w < NW; w++) { sc[w] = __expf(sc[w] - m); sum += sc[w]; }
    float inv = 1.f / sum;

    float o0 = 0.f, o1 = 0.f;
#pragma unroll
    for (int w = 0; w < NW; w++) {
        int tc = t + w - WINc;
        if (tc < 0 || tc >= Tc) continue;
        const float* vr = v + ((size_t)(b * Tc + tc) * Ec) + h * Dc;
        o0 += sc[w] * vr[lane];
        o1 += sc[w] * vr[lane + 32];
    }
    float* orow = out + ((size_t)(b * Tc + t) * Ec) + h * Dc;
    orow[lane]      = o0 * inv;
    orow[lane + 32] = o1 * inv;
}

// ---------------- launch orchestration -------------------------------------
extern "C" void kernel_launch(void* const* d_in, const int* in_sizes, int n_in,
                              void* d_out, int out_size) {
    const int*   tokens   = (const int*)  d_in[0];
    const int*   attmask  = (const int*)  d_in[1];
    const float* tok_emb  = (const float*)d_in[2];
    const float* pos_emb  = (const float*)d_in[3];
    const float* Wq       = (const float*)d_in[4];
    const float* Wk       = (const float*)d_in[5];
    const float* Wv       = (const float*)d_in[6];
    const float* Wo       = (const float*)d_in[7];
    const float* bo       = (const float*)d_in[8];
    const float* ln1_g    = (const float*)d_in[9];
    const float* ln1_b    = (const float*)d_in[10];
    const float* ln2_g    = (const float*)d_in[11];
    const float* ln2_b    = (const float*)d_in[12];
    const float* W1       = (const float*)d_in[13];
    const float* b1       = (const float*)d_in[14];
    const float* W2       = (const float*)d_in[15];
    const float* b2       = (const float*)d_in[16];

    float* x = (float*)d_out;   // residual stream lives in d_out

    float *h, *q, *k, *v, *ao, *ff;
    cudaGetSymbolAddress((void**)&h,  g_h);
    cudaGetSymbolAddress((void**)&q,  g_q);
    cudaGetSymbolAddress((void**)&k,  g_k);
    cudaGetSymbolAddress((void**)&v,  g_v);
    cudaGetSymbolAddress((void**)&ao, g_ao);
    cudaGetSymbolAddress((void**)&ff, g_ff);

    // x = tok_emb[tokens] + pos_emb
    embed_kernel<<<ROWS, 128>>>(tokens, tok_emb, pos_emb, x);

    dim3 gemmE(Ec / BN, ROWS / BM);    // (4, 64)
    dim3 gemmF(FFc / BN, ROWS / BM);   // (16, 64)
    int lnBlocks = (ROWS * 32 + 255) / 256;
    int attnBlocks = (Bc * Tc * Hc) / 4;   // 4 warps per 128-thread block

    for (int l = 0; l < Lc; l++) {
        const float* wq = Wq + (size_t)l * Ec * Ec;
        const float* wk = Wk + (size_t)l * Ec * Ec;
        const float* wv = Wv + (size_t)l * Ec * Ec;
        const float* wo = Wo + (size_t)l * Ec * Ec;
        const float* w1 = W1 + (size_t)l * Ec * FFc;
        const float* w2 = W2 + (size_t)l * FFc * Ec;

        // h = LN1(x)
        ln_kernel<<<lnBlocks, 256>>>(x, ln1_g + l * Ec, ln1_b + l * Ec, h);
        // q,k,v = h @ W{q,k,v}
        sgemm_kernel<0><<<gemmE, 256>>>(h, wq, nullptr, nullptr, q, ROWS, Ec, Ec);
        sgemm_kernel<0><<<gemmE, 256>>>(h, wk, nullptr, nullptr, k, ROWS, Ec, Ec);
        sgemm_kernel<0><<<gemmE, 256>>>(h, wv, nullptr, nullptr, v, ROWS, Ec, Ec);
        // ao = sliding-window attention
        attn_kernel<<<attnBlocks, 128>>>(q, k, v, attmask, ao);
        // x = x + ao @ Wo + bo
        sgemm_kernel<2><<<gemmE, 256>>>(ao, wo, bo + l * Ec, x, x, ROWS, Ec, Ec);
        // h = LN2(x)
        ln_kernel<<<lnBlocks, 256>>>(x, ln2_g + l * Ec, ln2_b + l * Ec, h);
        // ff = relu(h @ W1 + b1)
        sgemm_kernel<1><<<gemmF, 256>>>(h, w1, b1 + l * FFc, nullptr, ff, ROWS, FFc, Ec);
        // x = x + ff @ W2 + b2
        sgemm_kernel<2><<<gemmE, 256>>>(ff, w2, b2 + l * Ec, x, x, ROWS, Ec, FFc);
    }
    (void)in_sizes; (void)n_in; (void)out_size; (void)attmask;
}

// round 3
// speedup vs baseline: 2.4368x; 2.4368x over previous
#include <cuda_runtime.h>
#include <cuda_bf16.h>
#include <cstdint>

// ---------------- problem constants ----------------
#define Bc   2
#define Tc   4096
#define Ec   512
#define Hc   8
#define Dc   64
#define FFc  2048
#define Lc   2
#define WINc 16
#define NW   33
#define ROWS (Bc*Tc)      // 8192
#define EPSc 1e-5f
#define QKVN (3*Ec)       // 1536

// ---------------- scratch ----------------
__device__ __nv_bfloat16 g_hhi[(size_t)ROWS*Ec];
__device__ __nv_bfloat16 g_hlo[(size_t)ROWS*Ec];
__device__ float         g_qkv[(size_t)ROWS*QKVN];
__device__ __nv_bfloat16 g_aohi[(size_t)ROWS*Ec];
__device__ __nv_bfloat16 g_aolo[(size_t)ROWS*Ec];
__device__ __nv_bfloat16 g_ffhi[(size_t)ROWS*FFc];
__device__ __nv_bfloat16 g_fflo[(size_t)ROWS*FFc];
__device__ __nv_bfloat16 g_wthi[(size_t)FFc*Ec];
__device__ __nv_bfloat16 g_wtlo[(size_t)FFc*Ec];

// ---------------- helpers ----------------
__device__ __forceinline__ uint32_t smem_u32(const void* p) {
    uint32_t a;
    asm("{ .reg .u64 t; cvta.to.shared.u64 t, %1; cvt.u32.u64 %0, t; }" : "=r"(a) : "l"(p));
    return a;
}
#define SW128(x) ((x) ^ (((x) >> 3) & 0x70))

#define CP16(dst, src) \
    asm volatile("cp.async.cg.shared.global [%0], [%1], 16;" :: "r"(dst), "l"(src) : "memory")
#define CPCOMMIT() asm volatile("cp.async.commit_group;" ::: "memory")

__device__ __forceinline__ void ldmx4(uint32_t& r0, uint32_t& r1, uint32_t& r2, uint32_t& r3,
                                      uint32_t addr) {
    asm volatile("ldmatrix.sync.aligned.m8n8.x4.shared.b16 {%0,%1,%2,%3}, [%4];"
                 : "=r"(r0), "=r"(r1), "=r"(r2), "=r"(r3) : "r"(addr));
}
__device__ __forceinline__ void mma16816(float* c, uint32_t a0, uint32_t a1, uint32_t a2, uint32_t a3,
                                         uint32_t b0, uint32_t b1) {
    asm volatile("mma.sync.aligned.m16n8k16.row.col.f32.bf16.bf16.f32 "
                 "{%0,%1,%2,%3}, {%4,%5,%6,%7}, {%8,%9}, {%0,%1,%2,%3};"
                 : "+f"(c[0]), "+f"(c[1]), "+f"(c[2]), "+f"(c[3])
                 : "r"(a0), "r"(a1), "r"(a2), "r"(a3), "r"(b0), "r"(b1));
}

// ---------------- embedding ----------------
__global__ void embed_kernel(const int* __restrict__ tokens,
                             const float* __restrict__ tok_emb,
                             const float* __restrict__ pos_emb,
                             float* __restrict__ x) {
    int row = blockIdx.x;
    int t   = row & (Tc - 1);
    int tok = tokens[row];
    int e   = threadIdx.x * 4;
    float4 a = *(const float4*)(tok_emb + (size_t)tok * Ec + e);
    float4 p = *(const float4*)(pos_emb + (size_t)t   * Ec + e);
    a.x += p.x; a.y += p.y; a.z += p.z; a.w += p.w;
    *(float4*)(x + (size_t)row * Ec + e) = a;
}

// ---------------- layernorm -> split bf16 hi/lo ----------------
__global__ void ln_kernel(const float* __restrict__ x,
                          const float* __restrict__ g,
                          const float* __restrict__ b,
                          __nv_bfloat16* __restrict__ yhi,
                          __nv_bfloat16* __restrict__ ylo) {
    int warp = (blockIdx.x * blockDim.x + threadIdx.x) >> 5;
    int lane = threadIdx.x & 31;
    if (warp >= ROWS) return;
    const float* xr = x + (size_t)warp * Ec;
    float v[16];
    float s = 0.f;
#pragma unroll
    for (int i = 0; i < 16; i++) { v[i] = xr[lane + i * 32]; s += v[i]; }
#pragma unroll
    for (int o = 16; o > 0; o >>= 1) s += __shfl_xor_sync(0xffffffffu, s, o);
    float mean = s * (1.f / Ec);
    float ss = 0.f;
#pragma unroll
    for (int i = 0; i < 16; i++) { float d = v[i] - mean; ss += d * d; }
#pragma unroll
    for (int o = 16; o > 0; o >>= 1) ss += __shfl_xor_sync(0xffffffffu, ss, o);
    float inv = rsqrtf(ss * (1.f / Ec) + EPSc);
    size_t rb = (size_t)warp * Ec;
#pragma unroll
    for (int i = 0; i < 16; i++) {
        int idx = lane + i * 32;
        float r = (v[i] - mean) * inv * g[idx] + b[idx];
        __nv_bfloat16 h = __float2bfloat16(r);
        yhi[rb + idx] = h;
        ylo[rb + idx] = __float2bfloat16(r - __bfloat162float(h));
    }
}

// ---------------- weight transpose + split: W[K,N] -> Wt[N,K] hi/lo ----------
__global__ void wtrans_kernel(const float* __restrict__ W,
                              __nv_bfloat16* __restrict__ thi,
                              __nv_bfloat16* __restrict__ tlo,
                              int K, int N) {
    __shared__ float tile[32][33];
    int n0 = blockIdx.x * 32, k0 = blockIdx.y * 32;
    int tx = threadIdx.x, ty = threadIdx.y;   // 32 x 8
#pragma unroll
    for (int i = 0; i < 32; i += 8)
        tile[ty + i][tx] = W[(size_t)(k0 + ty + i) * N + n0 + tx];
    __syncthreads();
#pragma unroll
    for (int i = 0; i < 32; i += 8) {
        float v = tile[tx][ty + i];
        __nv_bfloat16 h = __float2bfloat16(v);
        size_t o = (size_t)(n0 + ty + i) * K + k0 + tx;
        thi[o] = h;
        tlo[o] = __float2bfloat16(v - __bfloat162float(h));
    }
}

// ---------------- mma.sync GEMM: C[M,N] = A[M,K] @ Wt[N,K]^T -----------------
// bf16x3: hi*hi + hi*lo + lo*hi, fp32 accumulate.
// EPI: 0 = fp32 out; 1 = bias+relu -> bf16 hi/lo; 2 = bias+residual fp32
#define GBM 128
#define GBN 128
#define GBK 64
#define AHI_OFF 0
#define ALO_OFF 16384
#define BHI_OFF 32768
#define BLO_OFF 49152
#define GSTG    65536
#define GEMM_SMEM (2*GSTG)

__device__ __forceinline__ void load_chunk(
    uint32_t base, int tid, int rowA0, int rowB0, int k0, int K,
    const __nv_bfloat16* __restrict__ Ahi, const __nv_bfloat16* __restrict__ Alo,
    const __nv_bfloat16* __restrict__ Bhi, const __nv_bfloat16* __restrict__ Blo) {
#pragma unroll
    for (int i = tid; i < 1024; i += 256) {            // 128 rows x 8 chunks of 16B
        int r = i >> 3, j = i & 7;
        uint32_t sw = SW128((uint32_t)((r << 7) + (j << 4)));
        size_t ga = (size_t)(rowA0 + r) * K + k0 + j * 8;
        size_t gb = (size_t)(rowB0 + r) * K + k0 + j * 8;
        CP16(base + AHI_OFF + sw, Ahi + ga);
        CP16(base + ALO_OFF + sw, Alo + ga);
        CP16(base + BHI_OFF + sw, Bhi + gb);
        CP16(base + BLO_OFF + sw, Blo + gb);
    }
}

template <int EPI>
__global__ __launch_bounds__(256, 1)
void mma_gemm(const __nv_bfloat16* __restrict__ Ahi, const __nv_bfloat16* __restrict__ Alo,
              const __nv_bfloat16* __restrict__ Bhi, const __nv_bfloat16* __restrict__ Blo,
              const float* __restrict__ bias, const float* __restrict__ res,
              float* __restrict__ outF,
              __nv_bfloat16* __restrict__ outHi, __nv_bfloat16* __restrict__ outLo,
              int N, int K) {
    extern __shared__ char smem[];
    uint32_t sb = smem_u32(smem);
    int tid = threadIdx.x, wid = tid >> 5, lane = tid & 31;

    int rowA0 = blockIdx.y * GBM;
    int rowB0 = blockIdx.x * GBN;
    int warpM0 = (wid >> 2) * 64;     // 2 warps in M
    int warpN0 = (wid & 3) * 32;      // 4 warps in N
    const int KC = K / GBK;

    float acc[4][4][4];               // [mfrag][nfrag][reg]
#pragma unroll
    for (int i = 0; i < 4; i++)
#pragma unroll
        for (int j = 0; j < 4; j++)
#pragma unroll
            for (int r = 0; r < 4; r++) acc[i][j][r] = 0.f;

    load_chunk(sb,        tid, rowA0, rowB0, 0,   K, Ahi, Alo, Bhi, Blo); CPCOMMIT();
    load_chunk(sb + GSTG, tid, rowA0, rowB0, GBK, K, Ahi, Alo, Bhi, Blo); CPCOMMIT();

    // ldmatrix lane addressing precompute
    int mat  = lane >> 3;             // 0..3
    int mrow = lane & 7;
    int rsel = (mat & 1) * 8 + mrow;  // row offset within 16-row frag
    int csel = mat >> 1;              // 16B chunk parity within k16

    for (int c = 0; c < KC; c++) {
        uint32_t base = sb + (uint32_t)(c & 1) * GSTG;
        if (c < KC - 1) asm volatile("cp.async.wait_group 1;" ::: "memory");
        else            asm volatile("cp.async.wait_group 0;" ::: "memory");
        __syncthreads();

#pragma unroll
        for (int kk = 0; kk < 4; kk++) {
            int chunk = 2 * kk + csel;
            // A fragments: 4 m-frags, hi+lo
            uint32_t ah[4][4], al[4][4];
#pragma unroll
            for (int mi = 0; mi < 4; mi++) {
                uint32_t byte = (uint32_t)((warpM0 + mi * 16 + rsel) << 7) + (chunk << 4);
                uint32_t sw = SW128(byte);
                ldmx4(ah[mi][0], ah[mi][1], ah[mi][2], ah[mi][3], base + AHI_OFF + sw);
                ldmx4(al[mi][0], al[mi][1], al[mi][2], al[mi][3], base + ALO_OFF + sw);
            }
            // B fragments: 2 pairs (each covers 16 n-rows -> 2 n8 frags), hi+lo
            uint32_t bh[4][2], bl[4][2];
#pragma unroll
            for (int bj = 0; bj < 2; bj++) {
                uint32_t byte = (uint32_t)((warpN0 + bj * 16 + rsel) << 7) + (chunk << 4);
                uint32_t sw = SW128(byte);
                uint32_t r0, r1, r2, r3;
                ldmx4(r0, r1, r2, r3, base + BHI_OFF + sw);
                bh[2*bj][0] = r0; bh[2*bj][1] = r2; bh[2*bj+1][0] = r1; bh[2*bj+1][1] = r3;
                ldmx4(r0, r1, r2, r3, base + BLO_OFF + sw);
                bl[2*bj][0] = r0; bl[2*bj][1] = r2; bl[2*bj+1][0] = r1; bl[2*bj+1][1] = r3;
            }
#pragma unroll
            for (int mi = 0; mi < 4; mi++)
#pragma unroll
                for (int nf = 0; nf < 4; nf++) {
                    mma16816(acc[mi][nf], ah[mi][0], ah[mi][1], ah[mi][2], ah[mi][3],
                             bh[nf][0], bh[nf][1]);
                    mma16816(acc[mi][nf], ah[mi][0], ah[mi][1], ah[mi][2], ah[mi][3],
                             bl[nf][0], bl[nf][1]);
                    mma16816(acc[mi][nf], al[mi][0], al[mi][1], al[mi][2], al[mi][3],
                             bh[nf][0], bh[nf][1]);
                }
        }
        __syncthreads();
        if (c + 2 < KC) {
            load_chunk(base, tid, rowA0, rowB0, (c + 2) * GBK, K, Ahi, Alo, Bhi, Blo);
            CPCOMMIT();
        }
    }

    // ---------------- epilogue ----------------
    int grp = lane >> 2;         // 0..7
    int qd  = lane & 3;          // 0..3
#pragma unroll
    for (int mi = 0; mi < 4; mi++) {
#pragma unroll
        for (int half = 0; half < 2; half++) {
            int m = rowA0 + warpM0 + mi * 16 + half * 8 + grp;
            size_t orow = (size_t)m * N;
#pragma unroll
            for (int nf = 0; nf < 4; nf++) {
                int n = rowB0 + warpN0 + nf * 8 + qd * 2;
                float v0 = acc[mi][nf][half * 2 + 0];
                float v1 = acc[mi][nf][half * 2 + 1];
                if (EPI == 0) {
                    float2 vv; vv.x = v0; vv.y = v1;
                    *(float2*)(outF + orow + n) = vv;
                } else if (EPI == 2) {
                    float2 rr = *(const float2*)(res + orow + n);
                    float2 vv;
                    vv.x = v0 + bias[n]     + rr.x;
                    vv.y = v1 + bias[n + 1] + rr.y;
                    *(float2*)(outF + orow + n) = vv;
                } else {
                    v0 = fmaxf(v0 + bias[n],     0.f);
                    v1 = fmaxf(v1 + bias[n + 1], 0.f);
                    __nv_bfloat16 h0 = __float2bfloat16(v0), h1 = __float2bfloat16(v1);
                    __nv_bfloat162 hh; hh.x = h0; hh.y = h1;
                    *(__nv_bfloat162*)(outHi + orow + n) = hh;
                    __nv_bfloat162 ll;
                    ll.x = __float2bfloat16(v0 - __bfloat162float(h0));
                    ll.y = __float2bfloat16(v1 - __bfloat162float(h1));
                    *(__nv_bfloat162*)(outLo + orow + n) = ll;
                }
            }
        }
    }
}

// ---------------- tiled sliding-window attention ----------------------------
#define ATT 64
#define AROWS (ATT + 2*WINc)   // 96
#define ATT_SMEM (2 * AROWS * Dc * 4)   // 49152

__global__ void attn_kernel(const float* __restrict__ qkv,
                            const int* __restrict__ mask,
                            __nv_bfloat16* __restrict__ aohi,
                            __nv_bfloat16* __restrict__ aolo) {
    extern __shared__ float sm[];
    float* sK = sm;
    float* sV = sm + AROWS * Dc;
    int bid  = blockIdx.x;
    int tile = bid & (Tc / ATT - 1);
    int h    = (bid >> 6) & (Hc - 1);
    int b    = bid >> 9;
    int t0   = tile * ATT;
    int tid  = threadIdx.x;

    for (int i = tid; i < AROWS * (Dc / 4); i += 256) {
        int r = i >> 4, j = i & 15;
        int tc = t0 - WINc + r;
        float4 k4 = make_float4(0.f, 0.f, 0.f, 0.f), v4 = k4;
        if (tc >= 0 && tc < Tc) {
            const float* kr = qkv + (size_t)(b * Tc + tc) * QKVN + Ec + h * Dc;
            const float* vr = qkv + (size_t)(b * Tc + tc) * QKVN + 2 * Ec + h * Dc;
            k4 = *(const float4*)(kr + j * 4);
            v4 = *(const float4*)(vr + j * 4);
        }
        *(float4*)(sK + r * Dc + j * 4) = k4;
        *(float4*)(sV + r * Dc + j * 4) = v4;
    }
    __syncthreads();

    int wid = tid >> 5, lane = tid & 31;
    for (int tt = wid; tt < ATT; tt += 8) {
        int t = t0 + tt;
        const float* qr = qkv + (size_t)(b * Tc + t) * QKVN + h * Dc;
        float q0 = qr[lane], q1 = qr[lane + 32];
        float sc[NW];
#pragma unroll
        for (int w = 0; w < NW; w++) {
            int tc = t + w - WINc;
            float s = -1e9f;
            if (tc >= 0 && tc < Tc && mask[b * Tc + tc] > 0) {
                const float* kr = sK + (tt + w) * Dc;
                float p = q0 * kr[lane] + q1 * kr[lane + 32];
#pragma unroll
                for (int o = 16; o > 0; o >>= 1) p += __shfl_xor_sync(0xffffffffu, p, o);
                s = p * 0.125f;
            }
            sc[w] = s;
        }
        float m = -1e9f;
#pragma unroll
        for (int w = 0; w < NW; w++) m = fmaxf(m, sc[w]);
        float sum = 0.f;
#pragma unroll
        for (int w = 0; w < NW; w++) { sc[w] = __expf(sc[w] - m); sum += sc[w]; }
        float inv = 1.f / sum;
        float o0 = 0.f, o1 = 0.f;
#pragma unroll
        for (int w = 0; w < NW; w++) {
            const float* vr = sV + (tt + w) * Dc;
            o0 += sc[w] * vr[lane];
            o1 += sc[w] * vr[lane + 32];
        }
        o0 *= inv; o1 *= inv;
        size_t ob = (size_t)(b * Tc + t) * Ec + h * Dc;
        __nv_bfloat16 h0 = __float2bfloat16(o0), h1 = __float2bfloat16(o1);
        aohi[ob + lane]      = h0;
        aohi[ob + lane + 32] = h1;
        aolo[ob + lane]      = __float2bfloat16(o0 - __bfloat162float(h0));
        aolo[ob + lane + 32] = __float2bfloat16(o1 - __bfloat162float(h1));
    }
}

// ---------------- orchestration ----------------
extern "C" void kernel_launch(void* const* d_in, const int* in_sizes, int n_in,
                              void* d_out, int out_size) {
    const int*   tokens  = (const int*)  d_in[0];
    const int*   attmask = (const int*)  d_in[1];
    const float* tok_emb = (const float*)d_in[2];
    const float* pos_emb = (const float*)d_in[3];
    const float* Wq      = (const float*)d_in[4];
    const float* Wk      = (const float*)d_in[5];
    const float* Wv      = (const float*)d_in[6];
    const float* Wo      = (const float*)d_in[7];
    const float* bo      = (const float*)d_in[8];
    const float* ln1_g   = (const float*)d_in[9];
    const float* ln1_b   = (const float*)d_in[10];
    const float* ln2_g   = (const float*)d_in[11];
    const float* ln2_b   = (const float*)d_in[12];
    const float* W1      = (const float*)d_in[13];
    const float* b1      = (const float*)d_in[14];
    const float* W2      = (const float*)d_in[15];
    const float* b2      = (const float*)d_in[16];

    float* x = (float*)d_out;

    __nv_bfloat16 *hhi, *hlo, *aohi, *aolo, *ffhi, *fflo, *wthi, *wtlo;
    float* qkv;
    cudaGetSymbolAddress((void**)&hhi,  g_hhi);
    cudaGetSymbolAddress((void**)&hlo,  g_hlo);
    cudaGetSymbolAddress((void**)&qkv,  g_qkv);
    cudaGetSymbolAddress((void**)&aohi, g_aohi);
    cudaGetSymbolAddress((void**)&aolo, g_aolo);
    cudaGetSymbolAddress((void**)&ffhi, g_ffhi);
    cudaGetSymbolAddress((void**)&fflo, g_fflo);
    cudaGetSymbolAddress((void**)&wthi, g_wthi);
    cudaGetSymbolAddress((void**)&wtlo, g_wtlo);

    cudaFuncSetAttribute(mma_gemm<0>, cudaFuncAttributeMaxDynamicSharedMemorySize, GEMM_SMEM);
    cudaFuncSetAttribute(mma_gemm<1>, cudaFuncAttributeMaxDynamicSharedMemorySize, GEMM_SMEM);
    cudaFuncSetAttribute(mma_gemm<2>, cudaFuncAttributeMaxDynamicSharedMemorySize, GEMM_SMEM);

    embed_kernel<<<ROWS, 128>>>(tokens, tok_emb, pos_emb, x);

    dim3 tb32(32, 8);
    for (int l = 0; l < Lc; l++) {
        const float* wq = Wq + (size_t)l * Ec * Ec;
        const float* wk = Wk + (size_t)l * Ec * Ec;
        const float* wv = Wv + (size_t)l * Ec * Ec;
        const float* wo = Wo + (size_t)l * Ec * Ec;
        const float* w1 = W1 + (size_t)l * Ec * FFc;
        const float* w2 = W2 + (size_t)l * FFc * Ec;

        // h = LN1(x)
        ln_kernel<<<1024, 256>>>(x, ln1_g + l * Ec, ln1_b + l * Ec, hhi, hlo);

        // fused QKV weights: Wt rows 0..511=Wq^T, 512..1023=Wk^T, 1024..1535=Wv^T
        wtrans_kernel<<<dim3(16, 16), tb32>>>(wq, wthi,                   wtlo,                   Ec, Ec);
        wtrans_kernel<<<dim3(16, 16), tb32>>>(wk, wthi + (size_t)Ec*Ec,   wtlo + (size_t)Ec*Ec,   Ec, Ec);
        wtrans_kernel<<<dim3(16, 16), tb32>>>(wv, wthi + (size_t)2*Ec*Ec, wtlo + (size_t)2*Ec*Ec, Ec, Ec);
        mma_gemm<0><<<dim3(QKVN / GBN, ROWS / GBM), 256, GEMM_SMEM>>>(
            hhi, hlo, wthi, wtlo, nullptr, nullptr, qkv, nullptr, nullptr, QKVN, Ec);

        attn_kernel<<<Bc * Hc * (Tc / ATT), 256, ATT_SMEM>>>(qkv, attmask, aohi, aolo);

        // x += ao @ Wo + bo
        wtrans_kernel<<<dim3(16, 16), tb32>>>(wo, wthi, wtlo, Ec, Ec);
        mma_gemm<2><<<dim3(Ec / GBN, ROWS / GBM), 256, GEMM_SMEM>>>(
            aohi, aolo, wthi, wtlo, bo + l * Ec, x, x, nullptr, nullptr, Ec, Ec);

        // h = LN2(x)
        ln_kernel<<<1024, 256>>>(x, ln2_g + l * Ec, ln2_b + l * Ec, hhi, hlo);

        // ff = relu(h @ W1 + b1)
        wtrans_kernel<<<dim3(FFc / 32, Ec / 32), tb32>>>(w1, wthi, wtlo, Ec, FFc);
        mma_gemm<1><<<dim3(FFc / GBN, ROWS / GBM), 256, GEMM_SMEM>>>(
            hhi, hlo, wthi, wtlo, b1 + l * FFc, nullptr, nullptr, ffhi, fflo, FFc, Ec);

        // x += ff @ W2 + b2
        wtrans_kernel<<<dim3(Ec / 32, FFc / 32), tb32>>>(w2, wthi, wtlo, FFc, Ec);
        mma_gemm<2><<<dim3(Ec / GBN, ROWS / GBM), 256, GEMM_SMEM>>>(
            ffhi, fflo, wthi, wtlo, b2 + l * Ec, x, x, nullptr, nullptr, Ec, FFc);
    }
    (void)in_sizes; (void)n_in; (void)out_size;
}

// round 4
// speedup vs baseline: 3.1480x; 1.2919x over previous
#include <cuda_runtime.h>
#include <cuda_fp16.h>
#include <cstdint>

// ---------------- problem constants ----------------
#define Bc   2
#define Tc   4096
#define Ec   512
#define Hc   8
#define Dc   64
#define FFc  2048
#define Lc   2
#define WINc 16
#define NW   33
#define ROWS (Bc*Tc)      // 8192
#define EPSc 1e-5f
#define QKVN (3*Ec)       // 1536

// ---------------- scratch ----------------
__device__ __half g_h  [(size_t)ROWS*Ec];     // LN output (fp16)
__device__ float  g_qkv[(size_t)ROWS*QKVN];
__device__ __half g_ao [(size_t)ROWS*Ec];     // attention out (fp16)
__device__ __half g_ff [(size_t)ROWS*FFc];    // FFN hidden (fp16)
__device__ __half g_wthi[(size_t)FFc*Ec];     // weight^T hi
__device__ __half g_wtlo[(size_t)FFc*Ec];     // weight^T lo

// ---------------- helpers ----------------
__device__ __forceinline__ uint32_t smem_u32(const void* p) {
    uint32_t a;
    asm("{ .reg .u64 t; cvta.to.shared.u64 t, %1; cvt.u32.u64 %0, t; }" : "=r"(a) : "l"(p));
    return a;
}
#define SW128(x) ((x) ^ (((x) >> 3) & 0x70))

#define CP16(dst, src) \
    asm volatile("cp.async.cg.shared.global [%0], [%1], 16;" :: "r"(dst), "l"(src) : "memory")
#define CPCOMMIT() asm volatile("cp.async.commit_group;" ::: "memory")

__device__ __forceinline__ void ldmx4(uint32_t& r0, uint32_t& r1, uint32_t& r2, uint32_t& r3,
                                      uint32_t addr) {
    asm volatile("ldmatrix.sync.aligned.m8n8.x4.shared.b16 {%0,%1,%2,%3}, [%4];"
                 : "=r"(r0), "=r"(r1), "=r"(r2), "=r"(r3) : "r"(addr));
}
__device__ __forceinline__ void mma16816(float* c, uint32_t a0, uint32_t a1, uint32_t a2, uint32_t a3,
                                         uint32_t b0, uint32_t b1) {
    asm volatile("mma.sync.aligned.m16n8k16.row.col.f32.f16.f16.f32 "
                 "{%0,%1,%2,%3}, {%4,%5,%6,%7}, {%8,%9}, {%0,%1,%2,%3};"
                 : "+f"(c[0]), "+f"(c[1]), "+f"(c[2]), "+f"(c[3])
                 : "r"(a0), "r"(a1), "r"(a2), "r"(a3), "r"(b0), "r"(b1));
}

// ---------------- embedding ----------------
__global__ void embed_kernel(const int* __restrict__ tokens,
                             const float* __restrict__ tok_emb,
                             const float* __restrict__ pos_emb,
                             float* __restrict__ x) {
    int row = blockIdx.x;
    int t   = row & (Tc - 1);
    int tok = tokens[row];
    int e   = threadIdx.x * 4;
    float4 a = *(const float4*)(tok_emb + (size_t)tok * Ec + e);
    float4 p = *(const float4*)(pos_emb + (size_t)t   * Ec + e);
    a.x += p.x; a.y += p.y; a.z += p.z; a.w += p.w;
    *(float4*)(x + (size_t)row * Ec + e) = a;
}

// ---------------- layernorm -> fp16 ----------------
__global__ void ln_kernel(const float* __restrict__ x,
                          const float* __restrict__ g,
                          const float* __restrict__ b,
                          __half* __restrict__ y) {
    int warp = (blockIdx.x * blockDim.x + threadIdx.x) >> 5;
    int lane = threadIdx.x & 31;
    if (warp >= ROWS) return;
    const float* xr = x + (size_t)warp * Ec;
    float v[16];
    float s = 0.f;
#pragma unroll
    for (int i = 0; i < 16; i++) { v[i] = xr[lane + i * 32]; s += v[i]; }
#pragma unroll
    for (int o = 16; o > 0; o >>= 1) s += __shfl_xor_sync(0xffffffffu, s, o);
    float mean = s * (1.f / Ec);
    float ss = 0.f;
#pragma unroll
    for (int i = 0; i < 16; i++) { float d = v[i] - mean; ss += d * d; }
#pragma unroll
    for (int o = 16; o > 0; o >>= 1) ss += __shfl_xor_sync(0xffffffffu, ss, o);
    float inv = rsqrtf(ss * (1.f / Ec) + EPSc);
    size_t rb = (size_t)warp * Ec;
#pragma unroll
    for (int i = 0; i < 16; i++) {
        int idx = lane + i * 32;
        y[rb + idx] = __float2half_rn((v[i] - mean) * inv * g[idx] + b[idx]);
    }
}

// ---------------- weight transpose + fp16 split: W[K,N] -> Wt[N,K] hi/lo -----
__global__ void wtrans_kernel(const float* __restrict__ W,
                              __half* __restrict__ thi,
                              __half* __restrict__ tlo,
                              int K, int N) {
    __shared__ float tile[32][33];
    int n0 = blockIdx.x * 32, k0 = blockIdx.y * 32;
    int tx = threadIdx.x, ty = threadIdx.y;   // 32 x 8
#pragma unroll
    for (int i = 0; i < 32; i += 8)
        tile[ty + i][tx] = W[(size_t)(k0 + ty + i) * N + n0 + tx];
    __syncthreads();
#pragma unroll
    for (int i = 0; i < 32; i += 8) {
        float v = tile[tx][ty + i];
        __half h = __float2half_rn(v);
        size_t o = (size_t)(n0 + ty + i) * K + k0 + tx;
        thi[o] = h;
        tlo[o] = __float2half_rn(v - __half2float(h));
    }
}

// ---------------- mma.sync GEMM: C[M,N] = A[M,K] @ Wt[N,K]^T -----------------
// fp16 asymmetric split: C = A*Bhi + A*Blo (A fp16-rounded, B split hi/lo).
// EPI: 0 = fp32 out; 1 = bias+relu -> fp16 out; 2 = bias+residual fp32
#define GBM 128
#define GBN 128
#define GBK 64
#define A_OFF   0
#define BHI_OFF 16384
#define BLO_OFF 32768
#define GSTG    49152
#define NSTAGE  3
#define GEMM_SMEM (NSTAGE*GSTG)

__device__ __forceinline__ void load_chunk(
    uint32_t base, int tid, int rowA0, int rowB0, int k0, int K,
    const __half* __restrict__ A,
    const __half* __restrict__ Bhi, const __half* __restrict__ Blo) {
#pragma unroll
    for (int i = tid; i < 1024; i += 256) {            // 128 rows x 8 chunks of 16B
        int r = i >> 3, j = i & 7;
        uint32_t sw = SW128((uint32_t)((r << 7) + (j << 4)));
        size_t ga = (size_t)(rowA0 + r) * K + k0 + j * 8;
        size_t gb = (size_t)(rowB0 + r) * K + k0 + j * 8;
        CP16(base + A_OFF   + sw, A   + ga);
        CP16(base + BHI_OFF + sw, Bhi + gb);
        CP16(base + BLO_OFF + sw, Blo + gb);
    }
}

template <int EPI>
__global__ __launch_bounds__(256, 1)
void mma_gemm(const __half* __restrict__ A,
              const __half* __restrict__ Bhi, const __half* __restrict__ Blo,
              const float* __restrict__ bias, const float* __restrict__ res,
              float* __restrict__ outF, __half* __restrict__ outH,
              int N, int K) {
    extern __shared__ char smem[];
    uint32_t sb = smem_u32(smem);
    int tid = threadIdx.x, wid = tid >> 5, lane = tid & 31;

    int rowA0 = blockIdx.y * GBM;
    int rowB0 = blockIdx.x * GBN;
    int warpM0 = (wid >> 2) * 64;     // 2 warps in M
    int warpN0 = (wid & 3) * 32;      // 4 warps in N
    const int KC = K / GBK;

    float acc[4][4][4];
#pragma unroll
    for (int i = 0; i < 4; i++)
#pragma unroll
        for (int j = 0; j < 4; j++)
#pragma unroll
            for (int r = 0; r < 4; r++) acc[i][j][r] = 0.f;

    load_chunk(sb,        tid, rowA0, rowB0, 0,   K, A, Bhi, Blo); CPCOMMIT();
    load_chunk(sb + GSTG, tid, rowA0, rowB0, GBK, K, A, Bhi, Blo); CPCOMMIT();

    int mat  = lane >> 3;
    int mrow = lane & 7;
    int rsel = (mat & 1) * 8 + mrow;
    int csel = mat >> 1;

    for (int c = 0; c < KC; c++) {
        uint32_t base = sb + (uint32_t)(c % NSTAGE) * GSTG;
        asm volatile("cp.async.wait_group 1;" ::: "memory");
        __syncthreads();
        if (c + 2 < KC) {   // issue next load BEFORE compute (buffer (c+2)%3 is free)
            load_chunk(sb + (uint32_t)((c + 2) % NSTAGE) * GSTG,
                       tid, rowA0, rowB0, (c + 2) * GBK, K, A, Bhi, Blo);
            CPCOMMIT();
        }

#pragma unroll
        for (int kk = 0; kk < 4; kk++) {
            int chunk = 2 * kk + csel;
            uint32_t ah[4][4];
#pragma unroll
            for (int mi = 0; mi < 4; mi++) {
                uint32_t sw = SW128((uint32_t)((warpM0 + mi * 16 + rsel) << 7) + (chunk << 4));
                ldmx4(ah[mi][0], ah[mi][1], ah[mi][2], ah[mi][3], base + A_OFF + sw);
            }
            uint32_t bh[4][2], bl[4][2];
#pragma unroll
            for (int bj = 0; bj < 2; bj++) {
                uint32_t sw = SW128((uint32_t)((warpN0 + bj * 16 + rsel) << 7) + (chunk << 4));
                uint32_t r0, r1, r2, r3;
                ldmx4(r0, r1, r2, r3, base + BHI_OFF + sw);
                bh[2*bj][0] = r0; bh[2*bj][1] = r2; bh[2*bj+1][0] = r1; bh[2*bj+1][1] = r3;
                ldmx4(r0, r1, r2, r3, base + BLO_OFF + sw);
                bl[2*bj][0] = r0; bl[2*bj][1] = r2; bl[2*bj+1][0] = r1; bl[2*bj+1][1] = r3;
            }
#pragma unroll
            for (int mi = 0; mi < 4; mi++)
#pragma unroll
                for (int nf = 0; nf < 4; nf++) {
                    mma16816(acc[mi][nf], ah[mi][0], ah[mi][1], ah[mi][2], ah[mi][3],
                             bh[nf][0], bh[nf][1]);
                    mma16816(acc[mi][nf], ah[mi][0], ah[mi][1], ah[mi][2], ah[mi][3],
                             bl[nf][0], bl[nf][1]);
                }
        }
        __syncthreads();   // all warps done with stage c before its buffer is refilled
    }

    // ---------------- epilogue ----------------
    int grp = lane >> 2;
    int qd  = lane & 3;
#pragma unroll
    for (int mi = 0; mi < 4; mi++) {
#pragma unroll
        for (int half = 0; half < 2; half++) {
            int m = rowA0 + warpM0 + mi * 16 + half * 8 + grp;
            size_t orow = (size_t)m * N;
#pragma unroll
            for (int nf = 0; nf < 4; nf++) {
                int n = rowB0 + warpN0 + nf * 8 + qd * 2;
                float v0 = acc[mi][nf][half * 2 + 0];
                float v1 = acc[mi][nf][half * 2 + 1];
                if (EPI == 0) {
                    float2 vv; vv.x = v0; vv.y = v1;
                    *(float2*)(outF + orow + n) = vv;
                } else if (EPI == 2) {
                    float2 rr = *(const float2*)(res + orow + n);
                    float2 vv;
                    vv.x = v0 + bias[n]     + rr.x;
                    vv.y = v1 + bias[n + 1] + rr.y;
                    *(float2*)(outF + orow + n) = vv;
                } else {
                    v0 = fmaxf(v0 + bias[n],     0.f);
                    v1 = fmaxf(v1 + bias[n + 1], 0.f);
                    __half2 hh;
                    hh.x = __float2half_rn(v0);
                    hh.y = __float2half_rn(v1);
                    *(__half2*)(outH + orow + n) = hh;
                }
            }
        }
    }
}

// ---------------- tiled sliding-window attention ----------------------------
#define ATT 64
#define AROWS (ATT + 2*WINc)   // 96
#define ATT_SMEM (2 * AROWS * Dc * 4)   // 49152

__global__ void attn_kernel(const float* __restrict__ qkv,
                            const int* __restrict__ mask,
                            __half* __restrict__ ao) {
    extern __shared__ float sm[];
    float* sK = sm;
    float* sV = sm + AROWS * Dc;
    int bid  = blockIdx.x;
    int tile = bid & (Tc / ATT - 1);
    int h    = (bid >> 6) & (Hc - 1);
    int b    = bid >> 9;
    int t0   = tile * ATT;
    int tid  = threadIdx.x;

    for (int i = tid; i < AROWS * (Dc / 4); i += 256) {
        int r = i >> 4, j = i & 15;
        int tc = t0 - WINc + r;
        float4 k4 = make_float4(0.f, 0.f, 0.f, 0.f), v4 = k4;
        if (tc >= 0 && tc < Tc) {
            const float* kr = qkv + (size_t)(b * Tc + tc) * QKVN + Ec + h * Dc;
            const float* vr = qkv + (size_t)(b * Tc + tc) * QKVN + 2 * Ec + h * Dc;
            k4 = *(const float4*)(kr + j * 4);
            v4 = *(const float4*)(vr + j * 4);
        }
        *(float4*)(sK + r * Dc + j * 4) = k4;
        *(float4*)(sV + r * Dc + j * 4) = v4;
    }
    __syncthreads();

    int wid = tid >> 5, lane = tid & 31;
    for (int tt = wid; tt < ATT; tt += 8) {
        int t = t0 + tt;
        const float* qr = qkv + (size_t)(b * Tc + t) * QKVN + h * Dc;
        float q0 = qr[lane], q1 = qr[lane + 32];
        float sc[NW];
#pragma unroll
        for (int w = 0; w < NW; w++) {
            int tc = t + w - WINc;
            float s = -1e9f;
            if (tc >= 0 && tc < Tc && mask[b * Tc + tc] > 0) {
                const float* kr = sK + (tt + w) * Dc;
                float p = q0 * kr[lane] + q1 * kr[lane + 32];
#pragma unroll
                for (int o = 16; o > 0; o >>= 1) p += __shfl_xor_sync(0xffffffffu, p, o);
                s = p * 0.125f;
            }
            sc[w] = s;
        }
        float m = -1e9f;
#pragma unroll
        for (int w = 0; w < NW; w++) m = fmaxf(m, sc[w]);
        float sum = 0.f;
#pragma unroll
        for (int w = 0; w < NW; w++) { sc[w] = __expf(sc[w] - m); sum += sc[w]; }
        float inv = 1.f / sum;
        float o0 = 0.f, o1 = 0.f;
#pragma unroll
        for (int w = 0; w < NW; w++) {
            const float* vr = sV + (tt + w) * Dc;
            o0 += sc[w] * vr[lane];
            o1 += sc[w] * vr[lane + 32];
        }
        size_t ob = (size_t)(b * Tc + t) * Ec + h * Dc;
        ao[ob + lane]      = __float2half_rn(o0 * inv);
        ao[ob + lane + 32] = __float2half_rn(o1 * inv);
    }
}

// ---------------- orchestration ----------------
extern "C" void kernel_launch(void* const* d_in, const int* in_sizes, int n_in,
                              void* d_out, int out_size) {
    const int*   tokens  = (const int*)  d_in[0];
    const int*   attmask = (const int*)  d_in[1];
    const float* tok_emb = (const float*)d_in[2];
    const float* pos_emb = (const float*)d_in[3];
    const float* Wq      = (const float*)d_in[4];
    const float* Wk      = (const float*)d_in[5];
    const float* Wv      = (const float*)d_in[6];
    const float* Wo      = (const float*)d_in[7];
    const float* bo      = (const float*)d_in[8];
    const float* ln1_g   = (const float*)d_in[9];
    const float* ln1_b   = (const float*)d_in[10];
    const float* ln2_g   = (const float*)d_in[11];
    const float* ln2_b   = (const float*)d_in[12];
    const float* W1      = (const float*)d_in[13];
    const float* b1      = (const float*)d_in[14];
    const float* W2      = (const float*)d_in[15];
    const float* b2      = (const float*)d_in[16];

    float* x = (float*)d_out;

    __half *h, *ao, *ff, *wthi, *wtlo;
    float* qkv;
    cudaGetSymbolAddress((void**)&h,    g_h);
    cudaGetSymbolAddress((void**)&qkv,  g_qkv);
    cudaGetSymbolAddress((void**)&ao,   g_ao);
    cudaGetSymbolAddress((void**)&ff,   g_ff);
    cudaGetSymbolAddress((void**)&wthi, g_wthi);
    cudaGetSymbolAddress((void**)&wtlo, g_wtlo);

    cudaFuncSetAttribute(mma_gemm<0>, cudaFuncAttributeMaxDynamicSharedMemorySize, GEMM_SMEM);
    cudaFuncSetAttribute(mma_gemm<1>, cudaFuncAttributeMaxDynamicSharedMemorySize, GEMM_SMEM);
    cudaFuncSetAttribute(mma_gemm<2>, cudaFuncAttributeMaxDynamicSharedMemorySize, GEMM_SMEM);

    embed_kernel<<<ROWS, 128>>>(tokens, tok_emb, pos_emb, x);

    dim3 tb32(32, 8);
    for (int l = 0; l < Lc; l++) {
        const float* wq = Wq + (size_t)l * Ec * Ec;
        const float* wk = Wk + (size_t)l * Ec * Ec;
        const float* wv = Wv + (size_t)l * Ec * Ec;
        const float* wo = Wo + (size_t)l * Ec * Ec;
        const float* w1 = W1 + (size_t)l * Ec * FFc;
        const float* w2 = W2 + (size_t)l * FFc * Ec;

        // h = LN1(x)
        ln_kernel<<<1024, 256>>>(x, ln1_g + l * Ec, ln1_b + l * Ec, h);

        // fused QKV weights
        wtrans_kernel<<<dim3(16, 16), tb32>>>(wq, wthi,                   wtlo,                   Ec, Ec);
        wtrans_kernel<<<dim3(16, 16), tb32>>>(wk, wthi + (size_t)Ec*Ec,   wtlo + (size_t)Ec*Ec,   Ec, Ec);
        wtrans_kernel<<<dim3(16, 16), tb32>>>(wv, wthi + (size_t)2*Ec*Ec, wtlo + (size_t)2*Ec*Ec, Ec, Ec);
        mma_gemm<0><<<dim3(QKVN / GBN, ROWS / GBM), 256, GEMM_SMEM>>>(
            h, wthi, wtlo, nullptr, nullptr, qkv, nullptr, QKVN, Ec);

        attn_kernel<<<Bc * Hc * (Tc / ATT), 256, ATT_SMEM>>>(qkv, attmask, ao);

        // x += ao @ Wo + bo
        wtrans_kernel<<<dim3(16, 16), tb32>>>(wo, wthi, wtlo, Ec, Ec);
        mma_gemm<2><<<dim3(Ec / GBN, ROWS / GBM), 256, GEMM_SMEM>>>(
            ao, wthi, wtlo, bo + l * Ec, x, x, nullptr, Ec, Ec);

        // h = LN2(x)
        ln_kernel<<<1024, 256>>>(x, ln2_g + l * Ec, ln2_b + l * Ec, h);

        // ff = relu(h @ W1 + b1)
        wtrans_kernel<<<dim3(FFc / 32, Ec / 32), tb32>>>(w1, wthi, wtlo, Ec, FFc);
        mma_gemm<1><<<dim3(FFc / GBN, ROWS / GBM), 256, GEMM_SMEM>>>(
            h, wthi, wtlo, b1 + l * FFc, nullptr, nullptr, ff, FFc, Ec);

        // x += ff @ W2 + b2
        wtrans_kernel<<<dim3(Ec / 32, FFc / 32), tb32>>>(w2, wthi, wtlo, FFc, Ec);
        mma_gemm<2><<<dim3(Ec / GBN, ROWS / GBM), 256, GEMM_SMEM>>>(
            ff, wthi, wtlo, b2 + l * Ec, x, x, nullptr, Ec, FFc);
    }
    (void)in_sizes; (void)n_in; (void)out_size;
}

// round 5
// speedup vs baseline: 3.4278x; 1.0889x over previous
#include <cuda_runtime.h>
#include <cuda_fp16.h>
#include <cstdint>

// ---------------- problem constants ----------------
#define Bc   2
#define Tc   4096
#define Ec   512
#define Hc   8
#define Dc   64
#define FFc  2048
#define Lc   2
#define WINc 16
#define NW   33
#define ROWS (Bc*Tc)      // 8192
#define EPSc 1e-5f
#define QKVN (3*Ec)       // 1536

// per-layer transposed-weight block (halfs): [qkv 1536x512][Wo 512x512][W1 2048x512][W2 512x2048]
#define WT_QKV_OFF 0
#define WT_WO_OFF  (3*Ec*Ec)                  // 786432
#define WT_W1_OFF  (4*Ec*Ec)                  // 1048576
#define WT_W2_OFF  (WT_W1_OFF + FFc*Ec)       // 2097152
#define WT_LAYER   (WT_W2_OFF + Ec*FFc)       // 3145728

// ---------------- scratch ----------------
__device__ __half g_h   [(size_t)ROWS*Ec];
__device__ __half g_qkv [(size_t)ROWS*QKVN];
__device__ __half g_ao  [(size_t)ROWS*Ec];
__device__ __half g_ff  [(size_t)ROWS*FFc];
__device__ __half g_wthi[(size_t)Lc*WT_LAYER];
__device__ __half g_wtlo[(size_t)Lc*WT_LAYER];

// ---------------- helpers ----------------
__device__ __forceinline__ uint32_t smem_u32(const void* p) {
    uint32_t a;
    asm("{ .reg .u64 t; cvta.to.shared.u64 t, %1; cvt.u32.u64 %0, t; }" : "=r"(a) : "l"(p));
    return a;
}
#define SW128(x) ((x) ^ (((x) >> 3) & 0x70))

#define CP16(dst, src) \
    asm volatile("cp.async.cg.shared.global [%0], [%1], 16;" :: "r"(dst), "l"(src) : "memory")
#define CPCOMMIT() asm volatile("cp.async.commit_group;" ::: "memory")

__device__ __forceinline__ void ldmx4(uint32_t& r0, uint32_t& r1, uint32_t& r2, uint32_t& r3,
                                      uint32_t addr) {
    asm volatile("ldmatrix.sync.aligned.m8n8.x4.shared.b16 {%0,%1,%2,%3}, [%4];"
                 : "=r"(r0), "=r"(r1), "=r"(r2), "=r"(r3) : "r"(addr));
}
__device__ __forceinline__ void mma16816(float* c, uint32_t a0, uint32_t a1, uint32_t a2, uint32_t a3,
                                         uint32_t b0, uint32_t b1) {
    asm volatile("mma.sync.aligned.m16n8k16.row.col.f32.f16.f16.f32 "
                 "{%0,%1,%2,%3}, {%4,%5,%6,%7}, {%8,%9}, {%0,%1,%2,%3};"
                 : "+f"(c[0]), "+f"(c[1]), "+f"(c[2]), "+f"(c[3])
                 : "r"(a0), "r"(a1), "r"(a2), "r"(a3), "r"(b0), "r"(b1));
}

// ---------------- embedding ----------------
__global__ void embed_kernel(const int* __restrict__ tokens,
                             const float* __restrict__ tok_emb,
                             const float* __restrict__ pos_emb,
                             float* __restrict__ x) {
    int row = blockIdx.x;
    int t   = row & (Tc - 1);
    int tok = tokens[row];
    int e   = threadIdx.x * 4;
    float4 a = *(const float4*)(tok_emb + (size_t)tok * Ec + e);
    float4 p = *(const float4*)(pos_emb + (size_t)t   * Ec + e);
    a.x += p.x; a.y += p.y; a.z += p.z; a.w += p.w;
    *(float4*)(x + (size_t)row * Ec + e) = a;
}

// ---------------- layernorm -> fp16 ----------------
__global__ void ln_kernel(const float* __restrict__ x,
                          const float* __restrict__ g,
                          const float* __restrict__ b,
                          __half* __restrict__ y) {
    int warp = (blockIdx.x * blockDim.x + threadIdx.x) >> 5;
    int lane = threadIdx.x & 31;
    if (warp >= ROWS) return;
    const float* xr = x + (size_t)warp * Ec;
    float v[16];
    float s = 0.f;
#pragma unroll
    for (int i = 0; i < 16; i++) { v[i] = xr[lane + i * 32]; s += v[i]; }
#pragma unroll
    for (int o = 16; o > 0; o >>= 1) s += __shfl_xor_sync(0xffffffffu, s, o);
    float mean = s * (1.f / Ec);
    float ss = 0.f;
#pragma unroll
    for (int i = 0; i < 16; i++) { float d = v[i] - mean; ss += d * d; }
#pragma unroll
    for (int o = 16; o > 0; o >>= 1) ss += __shfl_xor_sync(0xffffffffu, ss, o);
    float inv = rsqrtf(ss * (1.f / Ec) + EPSc);
    size_t rb = (size_t)warp * Ec;
#pragma unroll
    for (int i = 0; i < 16; i++) {
        int idx = lane + i * 32;
        y[rb + idx] = __float2half_rn((v[i] - mean) * inv * g[idx] + b[idx]);
    }
}

// ---------------- fused weight prep: all matrices, all layers ----------------
// blockIdx.y: 0=Wq 1=Wk 2=Wv 3=Wo 4=W1 5=W2 ; blockIdx.z = layer
__global__ void prep_kernel(const float* __restrict__ Wq, const float* __restrict__ Wk,
                            const float* __restrict__ Wv, const float* __restrict__ Wo,
                            const float* __restrict__ W1, const float* __restrict__ W2,
                            __half* __restrict__ thi, __half* __restrict__ tlo) {
    int l = blockIdx.z, y = blockIdx.y;
    int K = (y == 5) ? FFc : Ec;
    int N = (y == 4) ? FFc : Ec;
    int ntiles = N >> 5;
    int nt = blockIdx.x % ntiles;
    int kt = blockIdx.x / ntiles;
    if (kt >= (K >> 5)) return;

    const float* W; size_t doff;
    switch (y) {
        case 0: W = Wq + (size_t)l * Ec * Ec;  doff = WT_QKV_OFF;            break;
        case 1: W = Wk + (size_t)l * Ec * Ec;  doff = WT_QKV_OFF + Ec * Ec;  break;
        case 2: W = Wv + (size_t)l * Ec * Ec;  doff = WT_QKV_OFF + 2*Ec*Ec;  break;
        case 3: W = Wo + (size_t)l * Ec * Ec;  doff = WT_WO_OFF;             break;
        case 4: W = W1 + (size_t)l * Ec * FFc; doff = WT_W1_OFF;             break;
        default:W = W2 + (size_t)l * FFc * Ec; doff = WT_W2_OFF;             break;
    }
    doff += (size_t)l * WT_LAYER;

    __shared__ float tile[32][33];
    int n0 = nt * 32, k0 = kt * 32;
    int tx = threadIdx.x, ty = threadIdx.y;   // 32 x 8
#pragma unroll
    for (int i = 0; i < 32; i += 8)
        tile[ty + i][tx] = W[(size_t)(k0 + ty + i) * N + n0 + tx];
    __syncthreads();
#pragma unroll
    for (int i = 0; i < 32; i += 8) {
        float v = tile[tx][ty + i];
        __half h = __float2half_rn(v);
        size_t o = doff + (size_t)(n0 + ty + i) * K + k0 + tx;
        thi[o] = h;
        tlo[o] = __float2half_rn(v - __half2float(h));
    }
}

// ---------------- mma.sync GEMM: C[M,N] = A[M,K] @ Wt[N,K]^T -----------------
// fp16 asymmetric split: C = A*Bhi + A*Blo.
// EPI: 0 = fp16 out (qkv); 1 = bias+relu -> fp16; 2 = bias+residual fp32
#define GBM 128
#define GBN 128
#define GBK 64
#define A_OFF   0
#define BHI_OFF 16384
#define BLO_OFF 32768
#define GSTG    49152
#define NSTAGE  2
#define GEMM_SMEM (NSTAGE*GSTG)

__device__ __forceinline__ void load_chunk(
    uint32_t base, int tid, int rowA0, int rowB0, int k0, int K,
    const __half* __restrict__ A,
    const __half* __restrict__ Bhi, const __half* __restrict__ Blo) {
#pragma unroll
    for (int i = tid; i < 1024; i += 256) {
        int r = i >> 3, j = i & 7;
        uint32_t sw = SW128((uint32_t)((r << 7) + (j << 4)));
        size_t ga = (size_t)(rowA0 + r) * K + k0 + j * 8;
        size_t gb = (size_t)(rowB0 + r) * K + k0 + j * 8;
        CP16(base + A_OFF   + sw, A   + ga);
        CP16(base + BHI_OFF + sw, Bhi + gb);
        CP16(base + BLO_OFF + sw, Blo + gb);
    }
}

template <int EPI>
__global__ __launch_bounds__(256, 2)
void mma_gemm(const __half* __restrict__ A,
              const __half* __restrict__ Bhi, const __half* __restrict__ Blo,
              const float* __restrict__ bias, const float* __restrict__ res,
              float* __restrict__ outF, __half* __restrict__ outH,
              int N, int K) {
    extern __shared__ char smem[];
    uint32_t sb = smem_u32(smem);
    int tid = threadIdx.x, wid = tid >> 5, lane = tid & 31;

    int rowA0 = blockIdx.y * GBM;
    int rowB0 = blockIdx.x * GBN;
    int warpM0 = (wid >> 2) * 64;
    int warpN0 = (wid & 3) * 32;
    const int KC = K / GBK;

    float acc[4][4][4];
#pragma unroll
    for (int i = 0; i < 4; i++)
#pragma unroll
        for (int j = 0; j < 4; j++)
#pragma unroll
            for (int r = 0; r < 4; r++) acc[i][j][r] = 0.f;

    load_chunk(sb,        tid, rowA0, rowB0, 0,   K, A, Bhi, Blo); CPCOMMIT();
    load_chunk(sb + GSTG, tid, rowA0, rowB0, GBK, K, A, Bhi, Blo); CPCOMMIT();

    int mat  = lane >> 3;
    int mrow = lane & 7;
    int rsel = (mat & 1) * 8 + mrow;
    int csel = mat >> 1;

    for (int c = 0; c < KC; c++) {
        uint32_t base = sb + (uint32_t)(c & 1) * GSTG;
        if (c < KC - 1) asm volatile("cp.async.wait_group 1;" ::: "memory");
        else            asm volatile("cp.async.wait_group 0;" ::: "memory");  // last chunk MUST be complete
        __syncthreads();

#pragma unroll
        for (int kk = 0; kk < 4; kk++) {
            int chunk = 2 * kk + csel;
            uint32_t ah[4][4];
#pragma unroll
            for (int mi = 0; mi < 4; mi++) {
                uint32_t sw = SW128((uint32_t)((warpM0 + mi * 16 + rsel) << 7) + (chunk << 4));
                ldmx4(ah[mi][0], ah[mi][1], ah[mi][2], ah[mi][3], base + A_OFF + sw);
            }
            uint32_t bh[4][2], bl[4][2];
#pragma unroll
            for (int bj = 0; bj < 2; bj++) {
                uint32_t sw = SW128((uint32_t)((warpN0 + bj * 16 + rsel) << 7) + (chunk << 4));
                uint32_t r0, r1, r2, r3;
                ldmx4(r0, r1, r2, r3, base + BHI_OFF + sw);
                bh[2*bj][0] = r0; bh[2*bj][1] = r2; bh[2*bj+1][0] = r1; bh[2*bj+1][1] = r3;
                ldmx4(r0, r1, r2, r3, base + BLO_OFF + sw);
                bl[2*bj][0] = r0; bl[2*bj][1] = r2; bl[2*bj+1][0] = r1; bl[2*bj+1][1] = r3;
            }
#pragma unroll
            for (int mi = 0; mi < 4; mi++)
#pragma unroll
                for (int nf = 0; nf < 4; nf++) {
                    mma16816(acc[mi][nf], ah[mi][0], ah[mi][1], ah[mi][2], ah[mi][3],
                             bh[nf][0], bh[nf][1]);
                    mma16816(acc[mi][nf], ah[mi][0], ah[mi][1], ah[mi][2], ah[mi][3],
                             bl[nf][0], bl[nf][1]);
                }
        }
        __syncthreads();
        if (c + 2 < KC) {   // refill this buffer (now fully consumed)
            load_chunk(base, tid, rowA0, rowB0, (c + 2) * GBK, K, A, Bhi, Blo);
            CPCOMMIT();
        }
    }

    // ---------------- epilogue ----------------
    int grp = lane >> 2;
    int qd  = lane & 3;
#pragma unroll
    for (int mi = 0; mi < 4; mi++) {
#pragma unroll
        for (int half = 0; half < 2; half++) {
            int m = rowA0 + warpM0 + mi * 16 + half * 8 + grp;
            size_t orow = (size_t)m * N;
#pragma unroll
            for (int nf = 0; nf < 4; nf++) {
                int n = rowB0 + warpN0 + nf * 8 + qd * 2;
                float v0 = acc[mi][nf][half * 2 + 0];
                float v1 = acc[mi][nf][half * 2 + 1];
                if (EPI == 0) {
                    __half2 hh;
                    hh.x = __float2half_rn(v0);
                    hh.y = __float2half_rn(v1);
                    *(__half2*)(outH + orow + n) = hh;
                } else if (EPI == 2) {
                    float2 rr = *(const float2*)(res + orow + n);
                    float2 vv;
                    vv.x = v0 + bias[n]     + rr.x;
                    vv.y = v1 + bias[n + 1] + rr.y;
                    *(float2*)(outF + orow + n) = vv;
                } else {
                    v0 = fmaxf(v0 + bias[n],     0.f);
                    v1 = fmaxf(v1 + bias[n + 1], 0.f);
                    __half2 hh;
                    hh.x = __float2half_rn(v0);
                    hh.y = __float2half_rn(v1);
                    *(__half2*)(outH + orow + n) = hh;
                }
            }
        }
    }
}

// ---------------- tiled sliding-window attention (fp16 qkv) ------------------
#define ATT 64
#define AROWS (ATT + 2*WINc)   // 96

__global__ void attn_kernel(const __half* __restrict__ qkv,
                            const int* __restrict__ mask,
                            __half* __restrict__ ao) {
    __shared__ __half sK[AROWS * Dc];
    __shared__ __half sV[AROWS * Dc];
    int bid  = blockIdx.x;
    int tile = bid & (Tc / ATT - 1);
    int h    = (bid >> 6) & (Hc - 1);
    int b    = bid >> 9;
    int t0   = tile * ATT;
    int tid  = threadIdx.x;

    for (int i = tid; i < AROWS * (Dc / 4); i += 256) {   // 4 halves (8B) per item
        int r = i >> 4, j = i & 15;
        int tc = t0 - WINc + r;
        uint2 k2 = make_uint2(0u, 0u), v2 = k2;
        if (tc >= 0 && tc < Tc) {
            const __half* kr = qkv + (size_t)(b * Tc + tc) * QKVN + Ec + h * Dc;
            const __half* vr = qkv + (size_t)(b * Tc + tc) * QKVN + 2 * Ec + h * Dc;
            k2 = *(const uint2*)(kr + j * 4);
            v2 = *(const uint2*)(vr + j * 4);
        }
        *(uint2*)(sK + r * Dc + j * 4) = k2;
        *(uint2*)(sV + r * Dc + j * 4) = v2;
    }
    __syncthreads();

    int wid = tid >> 5, lane = tid & 31;
    for (int tt = wid; tt < ATT; tt += 8) {
        int t = t0 + tt;
        const __half* qr = qkv + (size_t)(b * Tc + t) * QKVN + h * Dc;
        float q0 = __half2float(qr[lane]), q1 = __half2float(qr[lane + 32]);
        float sc[NW];
#pragma unroll
        for (int w = 0; w < NW; w++) {
            int tc = t + w - WINc;
            float s = -1e9f;
            if (tc >= 0 && tc < Tc && mask[b * Tc + tc] > 0) {
                const __half* kr = sK + (tt + w) * Dc;
                float p = q0 * __half2float(kr[lane]) + q1 * __half2float(kr[lane + 32]);
#pragma unroll
                for (int o = 16; o > 0; o >>= 1) p += __shfl_xor_sync(0xffffffffu, p, o);
                s = p * 0.125f;
            }
            sc[w] = s;
        }
        float m = -1e9f;
#pragma unroll
        for (int w = 0; w < NW; w++) m = fmaxf(m, sc[w]);
        float sum = 0.f;
#pragma unroll
        for (int w = 0; w < NW; w++) { sc[w] = __expf(sc[w] - m); sum += sc[w]; }
        float inv = 1.f / sum;
        float o0 = 0.f, o1 = 0.f;
#pragma unroll
        for (int w = 0; w < NW; w++) {
            const __half* vr = sV + (tt + w) * Dc;
            o0 += sc[w] * __half2float(vr[lane]);
            o1 += sc[w] * __half2float(vr[lane + 32]);
        }
        size_t ob = (size_t)(b * Tc + t) * Ec + h * Dc;
        ao[ob + lane]      = __float2half_rn(o0 * inv);
        ao[ob + lane + 32] = __float2half_rn(o1 * inv);
    }
}

// ---------------- orchestration ----------------
extern "C" void kernel_launch(void* const* d_in, const int* in_sizes, int n_in,
                              void* d_out, int out_size) {
    const int*   tokens  = (const int*)  d_in[0];
    const int*   attmask = (const int*)  d_in[1];
    const float* tok_emb = (const float*)d_in[2];
    const float* pos_emb = (const float*)d_in[3];
    const float* Wq      = (const float*)d_in[4];
    const float* Wk      = (const float*)d_in[5];
    const float* Wv      = (const float*)d_in[6];
    const float* Wo      = (const float*)d_in[7];
    const float* bo      = (const float*)d_in[8];
    const float* ln1_g   = (const float*)d_in[9];
    const float* ln1_b   = (const float*)d_in[10];
    const float* ln2_g   = (const float*)d_in[11];
    const float* ln2_b   = (const float*)d_in[12];
    const float* W1      = (const float*)d_in[13];
    const float* b1      = (const float*)d_in[14];
    const float* W2      = (const float*)d_in[15];
    const float* b2      = (const float*)d_in[16];

    float* x = (float*)d_out;

    __half *h, *qkv, *ao, *ff, *wthi, *wtlo;
    cudaGetSymbolAddress((void**)&h,    g_h);
    cudaGetSymbolAddress((void**)&qkv,  g_qkv);
    cudaGetSymbolAddress((void**)&ao,   g_ao);
    cudaGetSymbolAddress((void**)&ff,   g_ff);
    cudaGetSymbolAddress((void**)&wthi, g_wthi);
    cudaGetSymbolAddress((void**)&wtlo, g_wtlo);

    cudaFuncSetAttribute(mma_gemm<0>, cudaFuncAttributeMaxDynamicSharedMemorySize, GEMM_SMEM);
    cudaFuncSetAttribute(mma_gemm<1>, cudaFuncAttributeMaxDynamicSharedMemorySize, GEMM_SMEM);
    cudaFuncSetAttribute(mma_gemm<2>, cudaFuncAttributeMaxDynamicSharedMemorySize, GEMM_SMEM);

    // all weights transposed+split up-front (one launch)
    prep_kernel<<<dim3(1024, 6, Lc), dim3(32, 8)>>>(Wq, Wk, Wv, Wo, W1, W2, wthi, wtlo);

    embed_kernel<<<ROWS, 128>>>(tokens, tok_emb, pos_emb, x);

    for (int l = 0; l < Lc; l++) {
        const __half* whi = wthi + (size_t)l * WT_LAYER;
        const __half* wlo = wtlo + (size_t)l * WT_LAYER;

        // h = LN1(x)
        ln_kernel<<<1024, 256>>>(x, ln1_g + l * Ec, ln1_b + l * Ec, h);

        // qkv = h @ [Wq|Wk|Wv]  (fp16 out)
        mma_gemm<0><<<dim3(QKVN / GBN, ROWS / GBM), 256, GEMM_SMEM>>>(
            h, whi + WT_QKV_OFF, wlo + WT_QKV_OFF, nullptr, nullptr, nullptr, qkv, QKVN, Ec);

        attn_kernel<<<Bc * Hc * (Tc / ATT), 256>>>(qkv, attmask, ao);

        // x += ao @ Wo + bo
        mma_gemm<2><<<dim3(Ec / GBN, ROWS / GBM), 256, GEMM_SMEM>>>(
            ao, whi + WT_WO_OFF, wlo + WT_WO_OFF, bo + l * Ec, x, x, nullptr, Ec, Ec);

        // h = LN2(x)
        ln_kernel<<<1024, 256>>>(x, ln2_g + l * Ec, ln2_b + l * Ec, h);

        // ff = relu(h @ W1 + b1)
        mma_gemm<1><<<dim3(FFc / GBN, ROWS / GBM), 256, GEMM_SMEM>>>(
            h, whi + WT_W1_OFF, wlo + WT_W1_OFF, b1 + l * FFc, nullptr, nullptr, ff, FFc, Ec);

        // x += ff @ W2 + b2
        mma_gemm<2><<<dim3(Ec / GBN, ROWS / GBM), 256, GEMM_SMEM>>>(
            ff, whi + WT_W2_OFF, wlo + WT_W2_OFF, b2 + l * Ec, x, x, nullptr, Ec, FFc);
    }
    (void)in_sizes; (void)n_in; (void)out_size;
}

// round 6
// speedup vs baseline: 4.0042x; 1.1682x over previous
#include <cuda_runtime.h>
#include <cuda_fp16.h>
#include <cstdint>

// ---------------- problem constants ----------------
#define Bc   2
#define Tc   4096
#define Ec   512
#define Hc   8
#define Dc   64
#define FFc  2048
#define Lc   2
#define WINc 16
#define NW   33
#define ROWS (Bc*Tc)      // 8192
#define EPSc 1e-5f
#define QKVN (3*Ec)       // 1536

#define WT_QKV_OFF 0
#define WT_WO_OFF  (3*Ec*Ec)
#define WT_W1_OFF  (4*Ec*Ec)
#define WT_W2_OFF  (WT_W1_OFF + FFc*Ec)
#define WT_LAYER   (WT_W2_OFF + Ec*FFc)

// ---------------- scratch ----------------
__device__ __half g_h   [(size_t)ROWS*Ec];
__device__ __half g_qkv [(size_t)ROWS*QKVN];
__device__ __half g_ao  [(size_t)ROWS*Ec];
__device__ __half g_ff  [(size_t)ROWS*FFc];
__device__ __half g_wthi[(size_t)Lc*WT_LAYER];
__device__ __half g_wtlo[(size_t)Lc*WT_LAYER];

// ---------------- helpers ----------------
__device__ __forceinline__ uint32_t smem_u32(const void* p) {
    uint32_t a;
    asm("{ .reg .u64 t; cvta.to.shared.u64 t, %1; cvt.u32.u64 %0, t; }" : "=r"(a) : "l"(p));
    return a;
}
#define SW128(x) ((x) ^ (((x) >> 3) & 0x70))

#define CP16(dst, src) \
    asm volatile("cp.async.cg.shared.global [%0], [%1], 16;" :: "r"(dst), "l"(src) : "memory")
#define CPCOMMIT() asm volatile("cp.async.commit_group;" ::: "memory")

__device__ __forceinline__ void ldmx4(uint32_t& r0, uint32_t& r1, uint32_t& r2, uint32_t& r3,
                                      uint32_t addr) {
    asm volatile("ldmatrix.sync.aligned.m8n8.x4.shared.b16 {%0,%1,%2,%3}, [%4];"
                 : "=r"(r0), "=r"(r1), "=r"(r2), "=r"(r3) : "r"(addr));
}
__device__ __forceinline__ void mma16816(float* c, const uint32_t* a, const uint32_t* b) {
    asm volatile("mma.sync.aligned.m16n8k16.row.col.f32.f16.f16.f32 "
                 "{%0,%1,%2,%3}, {%4,%5,%6,%7}, {%8,%9}, {%0,%1,%2,%3};"
                 : "+f"(c[0]), "+f"(c[1]), "+f"(c[2]), "+f"(c[3])
                 : "r"(a[0]), "r"(a[1]), "r"(a[2]), "r"(a[3]), "r"(b[0]), "r"(b[1]));
}

// ---------------- embedding ----------------
__global__ void embed_kernel(const int* __restrict__ tokens,
                             const float* __restrict__ tok_emb,
                             const float* __restrict__ pos_emb,
                             float* __restrict__ x) {
    int row = blockIdx.x;
    int t   = row & (Tc - 1);
    int tok = tokens[row];
    int e   = threadIdx.x * 4;
    float4 a = *(const float4*)(tok_emb + (size_t)tok * Ec + e);
    float4 p = *(const float4*)(pos_emb + (size_t)t   * Ec + e);
    a.x += p.x; a.y += p.y; a.z += p.z; a.w += p.w;
    *(float4*)(x + (size_t)row * Ec + e) = a;
}

// ---------------- layernorm -> fp16 ----------------
__global__ void ln_kernel(const float* __restrict__ x,
                          const float* __restrict__ g,
                          const float* __restrict__ b,
                          __half* __restrict__ y) {
    int warp = (blockIdx.x * blockDim.x + threadIdx.x) >> 5;
    int lane = threadIdx.x & 31;
    if (warp >= ROWS) return;
    const float* xr = x + (size_t)warp * Ec;
    float v[16];
    float s = 0.f;
#pragma unroll
    for (int i = 0; i < 16; i++) { v[i] = xr[lane + i * 32]; s += v[i]; }
#pragma unroll
    for (int o = 16; o > 0; o >>= 1) s += __shfl_xor_sync(0xffffffffu, s, o);
    float mean = s * (1.f / Ec);
    float ss = 0.f;
#pragma unroll
    for (int i = 0; i < 16; i++) { float d = v[i] - mean; ss += d * d; }
#pragma unroll
    for (int o = 16; o > 0; o >>= 1) ss += __shfl_xor_sync(0xffffffffu, ss, o);
    float inv = rsqrtf(ss * (1.f / Ec) + EPSc);
    size_t rb = (size_t)warp * Ec;
#pragma unroll
    for (int i = 0; i < 16; i++) {
        int idx = lane + i * 32;
        y[rb + idx] = __float2half_rn((v[i] - mean) * inv * g[idx] + b[idx]);
    }
}

// ---------------- fused weight prep ----------------
__global__ void prep_kernel(const float* __restrict__ Wq, const float* __restrict__ Wk,
                            const float* __restrict__ Wv, const float* __restrict__ Wo,
                            const float* __restrict__ W1, const float* __restrict__ W2,
                            __half* __restrict__ thi, __half* __restrict__ tlo) {
    int l = blockIdx.z, y = blockIdx.y;
    int K = (y == 5) ? FFc : Ec;
    int N = (y == 4) ? FFc : Ec;
    int ntiles = N >> 5;
    int nt = blockIdx.x % ntiles;
    int kt = blockIdx.x / ntiles;
    if (kt >= (K >> 5)) return;

    const float* W; size_t doff;
    switch (y) {
        case 0: W = Wq + (size_t)l * Ec * Ec;  doff = WT_QKV_OFF;            break;
        case 1: W = Wk + (size_t)l * Ec * Ec;  doff = WT_QKV_OFF + Ec * Ec;  break;
        case 2: W = Wv + (size_t)l * Ec * Ec;  doff = WT_QKV_OFF + 2*Ec*Ec;  break;
        case 3: W = Wo + (size_t)l * Ec * Ec;  doff = WT_WO_OFF;             break;
        case 4: W = W1 + (size_t)l * Ec * FFc; doff = WT_W1_OFF;             break;
        default:W = W2 + (size_t)l * FFc * Ec; doff = WT_W2_OFF;             break;
    }
    doff += (size_t)l * WT_LAYER;

    __shared__ float tile[32][33];
    int n0 = nt * 32, k0 = kt * 32;
    int tx = threadIdx.x, ty = threadIdx.y;
#pragma unroll
    for (int i = 0; i < 32; i += 8)
        tile[ty + i][tx] = W[(size_t)(k0 + ty + i) * N + n0 + tx];
    __syncthreads();
#pragma unroll
    for (int i = 0; i < 32; i += 8) {
        float v = tile[tx][ty + i];
        __half h = __float2half_rn(v);
        size_t o = doff + (size_t)(n0 + ty + i) * K + k0 + tx;
        thi[o] = h;
        tlo[o] = __float2half_rn(v - __half2float(h));
    }
}

// ---------------- mma.sync GEMM: CTA 128x256, warp 64x64 ---------------------
// fp16 asymmetric split: C = A*Bhi + A*Blo
// EPI: 0 = fp16 out; 1 = bias+relu -> fp16; 2 = bias+residual fp32
#define GBM 128
#define GBN 256
#define GBK 64
#define A_OFF   0
#define BHI_OFF 16384
#define BLO_OFF 49152
#define GSTG    81920
#define GEMM_SMEM (2*GSTG)   // 163840

__device__ __forceinline__ void load_chunk(
    uint32_t base, int tid, int rowA0, int rowB0, int k0, int K,
    const __half* __restrict__ A,
    const __half* __restrict__ Bhi, const __half* __restrict__ Blo) {
#pragma unroll
    for (int i = tid; i < 1024; i += 256) {            // A: 128 rows x 8 vec16
        int r = i >> 3, j = i & 7;
        uint32_t sw = SW128((uint32_t)((r << 7) + (j << 4)));
        CP16(base + A_OFF + sw, A + (size_t)(rowA0 + r) * K + k0 + j * 8);
    }
#pragma unroll
    for (int i = tid; i < 2048; i += 256) {            // B: 256 rows x 8 vec16 (hi+lo)
        int r = i >> 3, j = i & 7;
        uint32_t sw = SW128((uint32_t)((r << 7) + (j << 4)));
        size_t gb = (size_t)(rowB0 + r) * K + k0 + j * 8;
        CP16(base + BHI_OFF + sw, Bhi + gb);
        CP16(base + BLO_OFF + sw, Blo + gb);
    }
}

template <int EPI>
__global__ __launch_bounds__(256, 1)
void mma_gemm(const __half* __restrict__ A,
              const __half* __restrict__ Bhi, const __half* __restrict__ Blo,
              const float* __restrict__ bias, const float* __restrict__ res,
              float* __restrict__ outF, __half* __restrict__ outH,
              int N, int K) {
    extern __shared__ char smem[];
    uint32_t sb = smem_u32(smem);
    int tid = threadIdx.x, wid = tid >> 5, lane = tid & 31;

    int rowA0 = blockIdx.y * GBM;
    int rowB0 = blockIdx.x * GBN;
    int warpM0 = (wid >> 2) * 64;     // 2 warp rows
    int warpN0 = (wid & 3) * 64;      // 4 warp cols, 64 n each
    const int KC = K / GBK;

    float acc[4][8][4];
#pragma unroll
    for (int i = 0; i < 4; i++)
#pragma unroll
        for (int j = 0; j < 8; j++)
#pragma unroll
            for (int r = 0; r < 4; r++) acc[i][j][r] = 0.f;

    load_chunk(sb,        tid, rowA0, rowB0, 0,   K, A, Bhi, Blo); CPCOMMIT();
    load_chunk(sb + GSTG, tid, rowA0, rowB0, GBK, K, A, Bhi, Blo); CPCOMMIT();

    int mat  = lane >> 3;
    int mrow = lane & 7;
    int rsel = (mat & 1) * 8 + mrow;
    int csel = mat >> 1;

    for (int c = 0; c < KC; c++) {
        uint32_t base = sb + (uint32_t)(c & 1) * GSTG;
        if (c < KC - 1) asm volatile("cp.async.wait_group 1;" ::: "memory");
        else            asm volatile("cp.async.wait_group 0;" ::: "memory");
        __syncthreads();

#pragma unroll
        for (int kk = 0; kk < 4; kk++) {
            int chunk = 2 * kk + csel;
            uint32_t ah[4][4];
#pragma unroll
            for (int mi = 0; mi < 4; mi++) {
                uint32_t sw = SW128((uint32_t)((warpM0 + mi * 16 + rsel) << 7) + (chunk << 4));
                ldmx4(ah[mi][0], ah[mi][1], ah[mi][2], ah[mi][3], base + A_OFF + sw);
            }
            {   // hi pass
                uint32_t bh[8][2];
#pragma unroll
                for (int bj = 0; bj < 4; bj++) {
                    uint32_t sw = SW128((uint32_t)((warpN0 + bj * 16 + rsel) << 7) + (chunk << 4));
                    uint32_t r0, r1, r2, r3;
                    ldmx4(r0, r1, r2, r3, base + BHI_OFF + sw);
                    bh[2*bj][0] = r0; bh[2*bj][1] = r2; bh[2*bj+1][0] = r1; bh[2*bj+1][1] = r3;
                }
#pragma unroll
                for (int mi = 0; mi < 4; mi++)
#pragma unroll
                    for (int nf = 0; nf < 8; nf++)
                        mma16816(acc[mi][nf], ah[mi], bh[nf]);
            }
            {   // lo pass
                uint32_t bl[8][2];
#pragma unroll
                for (int bj = 0; bj < 4; bj++) {
                    uint32_t sw = SW128((uint32_t)((warpN0 + bj * 16 + rsel) << 7) + (chunk << 4));
                    uint32_t r0, r1, r2, r3;
                    ldmx4(r0, r1, r2, r3, base + BLO_OFF + sw);
                    bl[2*bj][0] = r0; bl[2*bj][1] = r2; bl[2*bj+1][0] = r1; bl[2*bj+1][1] = r3;
                }
#pragma unroll
                for (int mi = 0; mi < 4; mi++)
#pragma unroll
                    for (int nf = 0; nf < 8; nf++)
                        mma16816(acc[mi][nf], ah[mi], bl[nf]);
            }
        }
        __syncthreads();
        if (c + 2 < KC) {
            load_chunk(base, tid, rowA0, rowB0, (c + 2) * GBK, K, A, Bhi, Blo);
            CPCOMMIT();
        }
    }

    // ---------------- epilogue ----------------
    int grp = lane >> 2;
    int qd  = lane & 3;
#pragma unroll
    for (int mi = 0; mi < 4; mi++) {
#pragma unroll
        for (int half = 0; half < 2; half++) {
            int m = rowA0 + warpM0 + mi * 16 + half * 8 + grp;
            size_t orow = (size_t)m * N;
#pragma unroll
            for (int nf = 0; nf < 8; nf++) {
                int n = rowB0 + warpN0 + nf * 8 + qd * 2;
                float v0 = acc[mi][nf][half * 2 + 0];
                float v1 = acc[mi][nf][half * 2 + 1];
                if (EPI == 0) {
                    __half2 hh;
                    hh.x = __float2half_rn(v0);
                    hh.y = __float2half_rn(v1);
                    *(__half2*)(outH + orow + n) = hh;
                } else if (EPI == 2) {
                    float2 rr = *(const float2*)(res + orow + n);
                    float2 vv;
                    vv.x = v0 + bias[n]     + rr.x;
                    vv.y = v1 + bias[n + 1] + rr.y;
                    *(float2*)(outF + orow + n) = vv;
                } else {
                    v0 = fmaxf(v0 + bias[n],     0.f);
                    v1 = fmaxf(v1 + bias[n + 1], 0.f);
                    __half2 hh;
                    hh.x = __float2half_rn(v0);
                    hh.y = __float2half_rn(v1);
                    *(__half2*)(outH + orow + n) = hh;
                }
            }
        }
    }
}

// ---------------- sliding-window attention: lane-per-window ------------------
#define ATT 64
#define AROWS (ATT + 2*WINc)   // 96
#define KPITCH 66              // halves; 33 words -> conflict-free row stride

__global__ void attn_kernel(const __half* __restrict__ qkv,
                            const int* __restrict__ mask,
                            __half* __restrict__ ao) {
    __shared__ __half sK[AROWS * KPITCH];
    __shared__ __half sV[AROWS * KPITCH];
    __shared__ float  sp[8][40];          // per-warp probs (33 used)

    int bid  = blockIdx.x;
    int tile = bid & (Tc / ATT - 1);
    int h    = (bid >> 6) & (Hc - 1);
    int b    = bid >> 9;
    int t0   = tile * ATT;
    int tid  = threadIdx.x;

    // stage K/V (uint = 2 halves per item; row pitch 66 halves = 132B, 4B-aligned)
    for (int i = tid; i < AROWS * 32; i += 256) {
        int r = i >> 5, j = i & 31;
        int tc = t0 - WINc + r;
        uint32_t kv = 0, vv = 0;
        if (tc >= 0 && tc < Tc) {
            const __half* kr = qkv + (size_t)(b * Tc + tc) * QKVN + Ec + h * Dc;
            const __half* vr = qkv + (size_t)(b * Tc + tc) * QKVN + 2 * Ec + h * Dc;
            kv = *(const uint32_t*)(kr + j * 2);
            vv = *(const uint32_t*)(vr + j * 2);
        }
        *(uint32_t*)(sK + r * KPITCH + j * 2) = kv;
        *(uint32_t*)(sV + r * KPITCH + j * 2) = vv;
    }
    __syncthreads();

    int wid = tid >> 5, lane = tid & 31;
    for (int tt = wid; tt < ATT; tt += 8) {
        int t = t0 + tt;
        const __half2* q2 = (const __half2*)(qkv + (size_t)(b * Tc + t) * QKVN + h * Dc);

        // --- phase A: lane w computes score for window w = lane ---
        int w  = lane;
        int tc = t + w - WINc;
        bool valid = (tc >= 0) && (tc < Tc) && (mask[b * Tc + tc] > 0);
        float s = -1e9f;
        if (valid) {
            const __half2* kr = (const __half2*)(sK + (tt + w) * KPITCH);
            float p = 0.f;
#pragma unroll
            for (int j = 0; j < 32; j++) {
                float2 qf = __half22float2(q2[j]);
                float2 kf = __half22float2(kr[j]);
                p += qf.x * kf.x + qf.y * kf.y;
            }
            s = p * 0.125f;
        }
        // window 32 cooperatively (each lane does 2 dims, butterfly-reduce)
        float s32 = -1e9f;
        {
            int tc2 = t + WINc;
            bool v2 = (tc2 < Tc) && (mask[b * Tc + tc2] > 0);
            float2 qf = __half22float2(q2[lane]);
            float2 kf = __half22float2(*(const __half2*)(sK + (tt + 32) * KPITCH + 2 * lane));
            float pp = qf.x * kf.x + qf.y * kf.y;
#pragma unroll
            for (int o = 16; o > 0; o >>= 1) pp += __shfl_xor_sync(0xffffffffu, pp, o);
            if (v2) s32 = pp * 0.125f;
        }
        // softmax over 33 values
        float m = s;
#pragma unroll
        for (int o = 16; o > 0; o >>= 1) m = fmaxf(m, __shfl_xor_sync(0xffffffffu, m, o));
        m = fmaxf(m, s32);
        float e  = __expf(s - m);
        float es = e;
#pragma unroll
        for (int o = 16; o > 0; o >>= 1) es += __shfl_xor_sync(0xffffffffu, es, o);
        float e32 = __expf(s32 - m);
        float inv = 1.f / (es + e32);
        sp[wid][lane] = e;
        if (lane == 0) sp[wid][32] = e32;
        __syncwarp();

        // --- phase B: lane covers dims 2*lane, 2*lane+1 ---
        float ox = 0.f, oy = 0.f;
#pragma unroll
        for (int ww = 0; ww < NW; ww++) {
            float a = sp[wid][ww];
            float2 vf = __half22float2(*(const __half2*)(sV + (tt + ww) * KPITCH + 2 * lane));
            ox += a * vf.x;
            oy += a * vf.y;
        }
        size_t ob = (size_t)(b * Tc + t) * Ec + h * Dc;
        __half2 oh;
        oh.x = __float2half_rn(ox * inv);
        oh.y = __float2half_rn(oy * inv);
        *(__half2*)(ao + ob + 2 * lane) = oh;
        __syncwarp();
    }
}

// ---------------- orchestration ----------------
extern "C" void kernel_launch(void* const* d_in, const int* in_sizes, int n_in,
                              void* d_out, int out_size) {
    const int*   tokens  = (const int*)  d_in[0];
    const int*   attmask = (const int*)  d_in[1];
    const float* tok_emb = (const float*)d_in[2];
    const float* pos_emb = (const float*)d_in[3];
    const float* Wq      = (const float*)d_in[4];
    const float* Wk      = (const float*)d_in[5];
    const float* Wv      = (const float*)d_in[6];
    const float* Wo      = (const float*)d_in[7];
    const float* bo      = (const float*)d_in[8];
    const float* ln1_g   = (const float*)d_in[9];
    const float* ln1_b   = (const float*)d_in[10];
    const float* ln2_g   = (const float*)d_in[11];
    const float* ln2_b   = (const float*)d_in[12];
    const float* W1      = (const float*)d_in[13];
    const float* b1      = (const float*)d_in[14];
    const float* W2      = (const float*)d_in[15];
    const float* b2      = (const float*)d_in[16];

    float* x = (float*)d_out;

    __half *h, *qkv, *ao, *ff, *wthi, *wtlo;
    cudaGetSymbolAddress((void**)&h,    g_h);
    cudaGetSymbolAddress((void**)&qkv,  g_qkv);
    cudaGetSymbolAddress((void**)&ao,   g_ao);
    cudaGetSymbolAddress((void**)&ff,   g_ff);
    cudaGetSymbolAddress((void**)&wthi, g_wthi);
    cudaGetSymbolAddress((void**)&wtlo, g_wtlo);

    cudaFuncSetAttribute(mma_gemm<0>, cudaFuncAttributeMaxDynamicSharedMemorySize, GEMM_SMEM);
    cudaFuncSetAttribute(mma_gemm<1>, cudaFuncAttributeMaxDynamicSharedMemorySize, GEMM_SMEM);
    cudaFuncSetAttribute(mma_gemm<2>, cudaFuncAttributeMaxDynamicSharedMemorySize, GEMM_SMEM);

    prep_kernel<<<dim3(1024, 6, Lc), dim3(32, 8)>>>(Wq, Wk, Wv, Wo, W1, W2, wthi, wtlo);
    embed_kernel<<<ROWS, 128>>>(tokens, tok_emb, pos_emb, x);

    for (int l = 0; l < Lc; l++) {
        const __half* whi = wthi + (size_t)l * WT_LAYER;
        const __half* wlo = wtlo + (size_t)l * WT_LAYER;

        ln_kernel<<<1024, 256>>>(x, ln1_g + l * Ec, ln1_b + l * Ec, h);

        mma_gemm<0><<<dim3(QKVN / GBN, ROWS / GBM), 256, GEMM_SMEM>>>(
            h, whi + WT_QKV_OFF, wlo + WT_QKV_OFF, nullptr, nullptr, nullptr, qkv, QKVN, Ec);

        attn_kernel<<<Bc * Hc * (Tc / ATT), 256>>>(qkv, attmask, ao);

        mma_gemm<2><<<dim3(Ec / GBN, ROWS / GBM), 256, GEMM_SMEM>>>(
            ao, whi + WT_WO_OFF, wlo + WT_WO_OFF, bo + l * Ec, x, x, nullptr, Ec, Ec);

        ln_kernel<<<1024, 256>>>(x, ln2_g + l * Ec, ln2_b + l * Ec, h);

        mma_gemm<1><<<dim3(FFc / GBN, ROWS / GBM), 256, GEMM_SMEM>>>(
            h, whi + WT_W1_OFF, wlo + WT_W1_OFF, b1 + l * FFc, nullptr, nullptr, ff, FFc, Ec);

        mma_gemm<2><<<dim3(Ec / GBN, ROWS / GBM), 256, GEMM_SMEM>>>(
            ff, whi + WT_W2_OFF, wlo + WT_W2_OFF, b2 + l * Ec, x, x, nullptr, Ec, FFc);
    }
    (void)in_sizes; (void)n_in; (void)out_size;
}